// round 4
// baseline (speedup 1.0000x reference)
#include <cuda_runtime.h>
#include <cstdint>

// Problem constants (fixed by the reference):
//   z: [B=2048, TF=120, DL=16]  W: [TF, DL, P*CHUNK=672]  bias: [TF, 672]
//   out: [B, TF, P=16, 43] float32
#define TF     120
#define DL     16
#define PFEAT  16
#define CHUNK  42
#define CPAD   44          // per-feature columns padded to 44 for 16B-aligned pair loads
#define OUTC   43          // 1 gamma + 21 beta + 21 delta
#define OPB    (PFEAT*OUTC) // 688 floats per (b,t), contiguous in out
#define BT     32          // batch tile per block
#define NTH    512         // 32 b x 16 f, warp = one feature
#define SST    689         // staging row stride: 689 mod 32 = 17 (odd) -> conflict-free STS

// ---- packed f32x2 helpers (Blackwell sm_100a+) ----
__device__ __forceinline__ unsigned long long pack2(float lo, float hi) {
    unsigned long long r;
    asm("mov.b64 %0, {%1, %2};" : "=l"(r) : "f"(lo), "f"(hi));
    return r;
}
__device__ __forceinline__ void unpack2(unsigned long long v, float& lo, float& hi) {
    asm("mov.b64 {%0, %1}, %2;" : "=f"(lo), "=f"(hi) : "l"(v));
}
__device__ __forceinline__ unsigned long long ffma2(unsigned long long a,
                                                    unsigned long long b,
                                                    unsigned long long c) {
    unsigned long long d;
    asm("fma.rn.f32x2 %0, %1, %2, %3;" : "=l"(d) : "l"(a), "l"(b), "l"(c));
    return d;
}

__global__ __launch_bounds__(NTH)
void ddm_spline_kernel(const float* __restrict__ z,
                       const float* __restrict__ W,
                       const float* __restrict__ bias,
                       float* __restrict__ out)
{
    extern __shared__ float smem[];
    float* Ws  = smem;                       // [DL][PFEAT][CPAD] = 11264 floats
    float* bs  = Ws + DL * PFEAT * CPAD;     // [PFEAT][CPAD]     = 704
    float* zs  = bs + PFEAT * CPAD;          // [BT][DL+1]        = 544 (pad 17 -> conflict-free)
    float* stg = zs + BT * (DL + 1);         // [BT][SST]         = 22048

    const int tid = threadIdx.x;
    const int t   = blockIdx.y;
    const int b0  = blockIdx.x * BT;
    const int f   = tid >> 5;   // warp id = feature -> W LDS are broadcasts
    const int bl  = tid & 31;   // lane     = batch within tile

    // ---- load W[t] into padded smem (coalesced global reads) ----
    const float* Wt = W + (size_t)t * (DL * PFEAT * CHUNK);
    #pragma unroll
    for (int it = 0; it < (DL * PFEAT * CHUNK) / NTH; it++) {   // 10752/512 = 21 exact
        int i  = tid + it * NTH;
        int k  = i / (PFEAT * CHUNK);
        int o  = i - k * (PFEAT * CHUNK);
        int ff = o / CHUNK;
        int j  = o - ff * CHUNK;
        Ws[(k * PFEAT + ff) * CPAD + j] = Wt[i];
    }
    if (tid < DL * PFEAT) {                 // zero pad columns 42,43
        Ws[tid * CPAD + 42] = 0.f;
        Ws[tid * CPAD + 43] = 0.f;
    }
    // ---- bias[t] ----
    {
        const float* bt = bias + (size_t)t * (PFEAT * CHUNK);
        for (int i = tid; i < PFEAT * CHUNK; i += NTH) {
            int ff = i / CHUNK;
            int j  = i - ff * CHUNK;
            bs[ff * CPAD + j] = bt[i];
        }
        if (tid < PFEAT) { bs[tid * CPAD + 42] = 0.f; bs[tid * CPAD + 43] = 0.f; }
    }
    // ---- z tile: [BT][DL] -> padded smem (512 elements, one shot) ----
    {
        int bb = tid >> 4, kk = tid & 15;   // BT*DL == NTH
        zs[bb * (DL + 1) + kk] = z[((size_t)(b0 + bb) * TF + t) * DL + kk];
    }
    __syncthreads();

    // ---- GEMM: h[44] for (b0+bl, t, f) with f32x2 packed FMAs ----
    unsigned long long acc[22];
    {
        const ulonglong2* bp2 = reinterpret_cast<const ulonglong2*>(&bs[f * CPAD]);
        #pragma unroll
        for (int q = 0; q < 11; q++) {
            ulonglong2 v = bp2[q];
            acc[2 * q]     = v.x;
            acc[2 * q + 1] = v.y;
        }
    }
    {
        const float* zrow = &zs[bl * (DL + 1)];
        #pragma unroll
        for (int k = 0; k < DL; k++) {
            float zk = zrow[k];                       // conflict-free LDS (stride 17)
            unsigned long long zz = pack2(zk, zk);
            const ulonglong2* wr =
                reinterpret_cast<const ulonglong2*>(&Ws[(k * PFEAT + f) * CPAD]);
            #pragma unroll
            for (int q = 0; q < 11; q++) {            // LDS.128 broadcast (same addr per warp)
                ulonglong2 w = wr[q];
                acc[2 * q]     = ffma2(zz, w.x, acc[2 * q]);
                acc[2 * q + 1] = ffma2(zz, w.y, acc[2 * q + 1]);
            }
        }
    }

    float h[44];
    #pragma unroll
    for (int q = 0; q < 22; q++) unpack2(acc[q], h[2 * q], h[2 * q + 1]);

    // ---- transforms, write into staging row (conflict-free: lane stride 689 ≡ 17 mod 32) ----
    float* srow = &stg[bl * SST + f * OUTC];
    srow[0] = h[0];                                   // gamma
    #pragma unroll
    for (int i = 0; i < 21; i++) {                    // beta = softplus(h[1..21])
        float x = h[1 + i];
        srow[1 + i] = fmaxf(x, 0.f) + __logf(1.f + __expf(-fabsf(x)));
    }
    // softmax(h[22..41] / 0.1)
    float m = h[22];
    #pragma unroll
    for (int i = 1; i < 20; i++) m = fmaxf(m, h[22 + i]);
    float e[20];
    float sum = 0.f;
    #pragma unroll
    for (int i = 0; i < 20; i++) {
        e[i] = __expf((h[22 + i] - m) * 10.0f);
        sum += e[i];
    }
    float inv = __fdividef(1.0f, sum);
    // delta = [0, cumsum(s)]
    srow[22] = 0.f;
    float c = 0.f;
    #pragma unroll
    for (int i = 0; i < 20; i++) {
        c += e[i] * inv;
        srow[23 + i] = c;
    }
    __syncthreads();

    // ---- coalesced flush: per-b regions of 688 contiguous floats ----
    // scalar copy: LDS stride-1 (conflict-free) + STG.32 fully coalesced
    #pragma unroll 4
    for (int it = 0; it < (BT * OPB) / NTH; it++) {   // 22016/512 = 43 exact
        int i   = tid + it * NTH;
        int blc = i / OPB;
        int r   = i - blc * OPB;
        out[((b0 + blc) * TF + t) * OPB + r] = stg[blc * SST + r];
    }
}

extern "C" void kernel_launch(void* const* d_in, const int* in_sizes, int n_in,
                              void* d_out, int out_size) {
    const float* z    = (const float*)d_in[0];
    const float* W    = (const float*)d_in[1];
    const float* bias = (const float*)d_in[2];
    float* out        = (float*)d_out;

    const int B = in_sizes[0] / (TF * DL);   // 2048
    const size_t shmem =
        (size_t)(DL * PFEAT * CPAD + PFEAT * CPAD + BT * (DL + 1) + BT * SST) * sizeof(float);

    cudaFuncSetAttribute(ddm_spline_kernel,
                         cudaFuncAttributeMaxDynamicSharedMemorySize, (int)shmem);

    dim3 grid(B / BT, TF);   // b-tiles fastest -> W[t] stays L2-hot across concurrent blocks
    ddm_spline_kernel<<<grid, NTH, shmem>>>(z, W, bias, out);
}